// round 1
// baseline (speedup 1.0000x reference)
#include <cuda_runtime.h>
#include <math.h>

// Problem constants (MixtureOfExperts_67010079752265)
#define TOK_MAX 8192   // B*S = 4*2048
#define DIM     1024   // D
#define NEXP    4      // E
#define HID     4096   // H
// GEMM tiling
#define TM 128
#define TN 128
#define TK 16
#define SPAD 132       // smem row stride (132 = 4 mod 8 -> kills STS conflicts, keeps f4 align)

// ---------------- device scratch (no cudaMalloc allowed) ----------------
__device__ int   g_cnt[NEXP];
__device__ int   g_tok[NEXP * TOK_MAX];
__device__ float g_wt [NEXP * TOK_MAX];
__device__ float g_hbuf[(size_t)NEXP * TOK_MAX * HID];   // 512 MB fp32 intermediate

// ---------------- reset ----------------
__global__ void reset_cnt_kernel() {
    if (threadIdx.x < NEXP) g_cnt[threadIdx.x] = 0;
}

// ---------------- router: logits, softmax-top2, renorm, compaction ----------------
__global__ void router_kernel(const float* __restrict__ x,
                              const float* __restrict__ Wr) {
    const int t   = blockIdx.x;     // one block per token
    const int tid = threadIdx.x;    // 128 threads
    float acc0 = 0.f, acc1 = 0.f, acc2 = 0.f, acc3 = 0.f;
    const float4* wr4 = (const float4*)Wr;   // Wr is [D,E=4], row d is one float4
    const float*  xr  = x + (size_t)t * DIM;
    for (int d = tid; d < DIM; d += 128) {
        float xv = xr[d];
        float4 w = wr4[d];
        acc0 = fmaf(xv, w.x, acc0);
        acc1 = fmaf(xv, w.y, acc1);
        acc2 = fmaf(xv, w.z, acc2);
        acc3 = fmaf(xv, w.w, acc3);
    }
    __shared__ float sr[4][128];
    sr[0][tid] = acc0; sr[1][tid] = acc1; sr[2][tid] = acc2; sr[3][tid] = acc3;
    __syncthreads();
    for (int s = 64; s > 0; s >>= 1) {
        if (tid < s) {
            sr[0][tid] += sr[0][tid + s];
            sr[1][tid] += sr[1][tid + s];
            sr[2][tid] += sr[2][tid + s];
            sr[3][tid] += sr[3][tid + s];
        }
        __syncthreads();
    }
    if (tid == 0) {
        float l[4] = { sr[0][0], sr[1][0], sr[2][0], sr[3][0] };
        int i0 = 0;
        #pragma unroll
        for (int e = 1; e < 4; e++) if (l[e] > l[i0]) i0 = e;
        int i1 = -1;
        #pragma unroll
        for (int e = 0; e < 4; e++) {
            if (e == i0) continue;
            if (i1 < 0 || l[e] > l[i1]) i1 = e;
        }
        // renormalized top-2 softmax weights = exp(l_i)/(exp(l_i0)+exp(l_i1))
        float e1 = expf(l[i1] - l[i0]);
        float w0 = 1.0f / (1.0f + e1);
        float w1 = e1 / (1.0f + e1);
        int s0 = atomicAdd(&g_cnt[i0], 1);
        g_tok[i0 * TOK_MAX + s0] = t;
        g_wt [i0 * TOK_MAX + s0] = w0;
        int s1 = atomicAdd(&g_cnt[i1], 1);
        g_tok[i1 * TOK_MAX + s1] = t;
        g_wt [i1 * TOK_MAX + s1] = w1;
    }
}

// ---------------- GEMM1: h = relu(Xg @ W1_e + b1_e)  [M x HID], K = DIM ----------------
__global__ void __launch_bounds__(256)
gemm1_kernel(const float* __restrict__ x,
             const float* __restrict__ W1,
             const float* __restrict__ b1) {
    const int e   = blockIdx.z;
    const int cnt = g_cnt[e];
    const int m0  = blockIdx.x * TM;
    if (m0 >= cnt) return;
    const int n0  = blockIdx.y * TN;
    const int tid = threadIdx.x;

    __shared__ float As[TK][SPAD];
    __shared__ float Bs[TK][SPAD];

    // A-load mapping: 2 float4 per thread (128 rows x 16 K = 512 f4)
    const int ar0 = tid >> 2;            // rows 0..63
    const int ar1 = ar0 + 64;            // rows 64..127
    const int akv = (tid & 3) * 4;       // K sub-offset (0,4,8,12)
    const int tok0 = (m0 + ar0 < cnt) ? g_tok[e * TOK_MAX + m0 + ar0] : -1;
    const int tok1 = (m0 + ar1 < cnt) ? g_tok[e * TOK_MAX + m0 + ar1] : -1;

    // B-load mapping: 2 float4 per thread (16 K x 128 N = 512 f4)
    const int bk = tid >> 5;             // K rows 0..7 (+8 for second)
    const int bc = (tid & 31) * 4;       // N offset
    const float* Bg = W1 + (size_t)e * DIM * HID + n0;

    const int tm = (tid >> 4) * 8;
    const int tn = (tid & 15) * 8;

    float acc[8][8];
    #pragma unroll
    for (int i = 0; i < 8; i++)
        #pragma unroll
        for (int j = 0; j < 8; j++) acc[i][j] = 0.f;

    float4 pa0, pa1, pb0, pb1;
    // prefetch k0 = 0
    pa0 = (tok0 >= 0) ? *(const float4*)(x + (size_t)tok0 * DIM + akv)
                      : make_float4(0.f, 0.f, 0.f, 0.f);
    pa1 = (tok1 >= 0) ? *(const float4*)(x + (size_t)tok1 * DIM + akv)
                      : make_float4(0.f, 0.f, 0.f, 0.f);
    pb0 = *(const float4*)(Bg + (size_t)(bk    ) * HID + bc);
    pb1 = *(const float4*)(Bg + (size_t)(bk + 8) * HID + bc);

    for (int k0 = 0; k0 < DIM; k0 += TK) {
        // store staged tile
        As[akv + 0][ar0] = pa0.x; As[akv + 1][ar0] = pa0.y;
        As[akv + 2][ar0] = pa0.z; As[akv + 3][ar0] = pa0.w;
        As[akv + 0][ar1] = pa1.x; As[akv + 1][ar1] = pa1.y;
        As[akv + 2][ar1] = pa1.z; As[akv + 3][ar1] = pa1.w;
        *(float4*)&Bs[bk    ][bc] = pb0;
        *(float4*)&Bs[bk + 8][bc] = pb1;
        __syncthreads();

        int kn = k0 + TK;
        if (kn < DIM) {
            pa0 = (tok0 >= 0) ? *(const float4*)(x + (size_t)tok0 * DIM + kn + akv)
                              : make_float4(0.f, 0.f, 0.f, 0.f);
            pa1 = (tok1 >= 0) ? *(const float4*)(x + (size_t)tok1 * DIM + kn + akv)
                              : make_float4(0.f, 0.f, 0.f, 0.f);
            pb0 = *(const float4*)(Bg + (size_t)(kn + bk    ) * HID + bc);
            pb1 = *(const float4*)(Bg + (size_t)(kn + bk + 8) * HID + bc);
        }

        #pragma unroll
        for (int kk = 0; kk < TK; kk++) {
            float4 a0 = *(const float4*)&As[kk][tm];
            float4 a1 = *(const float4*)&As[kk][tm + 4];
            float4 b0 = *(const float4*)&Bs[kk][tn];
            float4 b1v = *(const float4*)&Bs[kk][tn + 4];
            float a[8] = { a0.x, a0.y, a0.z, a0.w, a1.x, a1.y, a1.z, a1.w };
            float b[8] = { b0.x, b0.y, b0.z, b0.w, b1v.x, b1v.y, b1v.z, b1v.w };
            #pragma unroll
            for (int i = 0; i < 8; i++)
                #pragma unroll
                for (int j = 0; j < 8; j++)
                    acc[i][j] = fmaf(a[i], b[j], acc[i][j]);
        }
        __syncthreads();
    }

    // epilogue: bias + relu -> g_hbuf
    float bb[8];
    #pragma unroll
    for (int j = 0; j < 8; j++) bb[j] = b1[e * HID + n0 + tn + j];
    float* hb = g_hbuf + (size_t)e * TOK_MAX * HID;
    #pragma unroll
    for (int i = 0; i < 8; i++) {
        int m = m0 + tm + i;
        if (m < cnt) {
            float* row = hb + (size_t)m * HID + n0 + tn;
            float4 v0, v1;
            v0.x = fmaxf(acc[i][0] + bb[0], 0.f);
            v0.y = fmaxf(acc[i][1] + bb[1], 0.f);
            v0.z = fmaxf(acc[i][2] + bb[2], 0.f);
            v0.w = fmaxf(acc[i][3] + bb[3], 0.f);
            v1.x = fmaxf(acc[i][4] + bb[4], 0.f);
            v1.y = fmaxf(acc[i][5] + bb[5], 0.f);
            v1.z = fmaxf(acc[i][6] + bb[6], 0.f);
            v1.w = fmaxf(acc[i][7] + bb[7], 0.f);
            *(float4*)(row)     = v0;
            *(float4*)(row + 4) = v1;
        }
    }
}

// ---------------- GEMM2: out[tok] += w * (h @ W2_e + b2_e)  [M x DIM], K = HID ----------------
__global__ void __launch_bounds__(256)
gemm2_kernel(const float* __restrict__ W2,
             const float* __restrict__ b2,
             float* __restrict__ out) {
    const int e   = blockIdx.z;
    const int cnt = g_cnt[e];
    const int m0  = blockIdx.x * TM;
    if (m0 >= cnt) return;
    const int n0  = blockIdx.y * TN;
    const int tid = threadIdx.x;

    __shared__ float As[TK][SPAD];
    __shared__ float Bs[TK][SPAD];

    const int ar0 = tid >> 2;
    const int ar1 = ar0 + 64;
    const int akv = (tid & 3) * 4;
    const float* hb = g_hbuf + (size_t)e * TOK_MAX * HID;
    const float* arow0 = hb + (size_t)(m0 + ar0) * HID;   // rows beyond cnt read stale
    const float* arow1 = hb + (size_t)(m0 + ar1) * HID;   // data; never stored below

    const int bk = tid >> 5;
    const int bc = (tid & 31) * 4;
    const float* Bg = W2 + (size_t)e * HID * DIM + n0;

    const int tm = (tid >> 4) * 8;
    const int tn = (tid & 15) * 8;

    float acc[8][8];
    #pragma unroll
    for (int i = 0; i < 8; i++)
        #pragma unroll
        for (int j = 0; j < 8; j++) acc[i][j] = 0.f;

    float4 pa0, pa1, pb0, pb1;
    pa0 = *(const float4*)(arow0 + akv);
    pa1 = *(const float4*)(arow1 + akv);
    pb0 = *(const float4*)(Bg + (size_t)(bk    ) * DIM + bc);
    pb1 = *(const float4*)(Bg + (size_t)(bk + 8) * DIM + bc);

    for (int k0 = 0; k0 < HID; k0 += TK) {
        As[akv + 0][ar0] = pa0.x; As[akv + 1][ar0] = pa0.y;
        As[akv + 2][ar0] = pa0.z; As[akv + 3][ar0] = pa0.w;
        As[akv + 0][ar1] = pa1.x; As[akv + 1][ar1] = pa1.y;
        As[akv + 2][ar1] = pa1.z; As[akv + 3][ar1] = pa1.w;
        *(float4*)&Bs[bk    ][bc] = pb0;
        *(float4*)&Bs[bk + 8][bc] = pb1;
        __syncthreads();

        int kn = k0 + TK;
        if (kn < HID) {
            pa0 = *(const float4*)(arow0 + kn + akv);
            pa1 = *(const float4*)(arow1 + kn + akv);
            pb0 = *(const float4*)(Bg + (size_t)(kn + bk    ) * DIM + bc);
            pb1 = *(const float4*)(Bg + (size_t)(kn + bk + 8) * DIM + bc);
        }

        #pragma unroll
        for (int kk = 0; kk < TK; kk++) {
            float4 a0 = *(const float4*)&As[kk][tm];
            float4 a1 = *(const float4*)&As[kk][tm + 4];
            float4 b0 = *(const float4*)&Bs[kk][tn];
            float4 b1v = *(const float4*)&Bs[kk][tn + 4];
            float a[8] = { a0.x, a0.y, a0.z, a0.w, a1.x, a1.y, a1.z, a1.w };
            float b[8] = { b0.x, b0.y, b0.z, b0.w, b1v.x, b1v.y, b1v.z, b1v.w };
            #pragma unroll
            for (int i = 0; i < 8; i++)
                #pragma unroll
                for (int j = 0; j < 8; j++)
                    acc[i][j] = fmaf(a[i], b[j], acc[i][j]);
        }
        __syncthreads();
    }

    float bb[8];
    #pragma unroll
    for (int j = 0; j < 8; j++) bb[j] = b2[e * DIM + n0 + tn + j];
    #pragma unroll
    for (int i = 0; i < 8; i++) {
        int m = m0 + tm + i;
        if (m < cnt) {
            int   tok = g_tok[e * TOK_MAX + m];
            float w   = g_wt [e * TOK_MAX + m];
            float* orow = out + (size_t)tok * DIM + n0 + tn;
            #pragma unroll
            for (int j = 0; j < 8; j++)
                atomicAdd(&orow[j], w * (acc[i][j] + bb[j]));
        }
    }
}

// ---------------- launch ----------------
extern "C" void kernel_launch(void* const* d_in, const int* in_sizes, int n_in,
                              void* d_out, int out_size) {
    const float* x  = (const float*)d_in[0];
    const float* Wr = (const float*)d_in[1];
    const float* W1 = (const float*)d_in[2];
    const float* b1 = (const float*)d_in[3];
    const float* W2 = (const float*)d_in[4];
    const float* b2 = (const float*)d_in[5];
    float* out = (float*)d_out;

    const int T = in_sizes[0] / DIM;   // 8192 tokens

    // zero output (out is poisoned; also covers aux_loss tail element)
    cudaMemsetAsync(out, 0, (size_t)out_size * sizeof(float));

    reset_cnt_kernel<<<1, 32>>>();
    router_kernel<<<T, 128>>>(x, Wr);

    dim3 g1((T + TM - 1) / TM, HID / TN, NEXP);
    gemm1_kernel<<<g1, 256>>>(x, W1, b1);

    dim3 g2((T + TM - 1) / TM, DIM / TN, NEXP);
    gemm2_kernel<<<g2, 256>>>(W2, b2, out);
}

// round 4
// speedup vs baseline: 2.4286x; 2.4286x over previous
#include <cuda_runtime.h>
#include <cuda_bf16.h>
#include <math.h>
#include <stdint.h>

// Problem constants (MixtureOfExperts_67010079752265)
#define TOK_MAX 8192
#define DIM     1024
#define NEXP    4
#define HID     4096

// GEMM tiling (mma.sync m16n8k16 bf16)
#define TM 128
#define TN 128
#define TK 32            // bf16 k-elems per chunk
// smem layout (bytes), per buffer:
//   A_hi [128][40] bf16 = 10240 ; A_lo +10240
//   B_hi [32][136] bf16 = 8704  ; B_lo +8704
#define A_STR 80         // bytes per A row (40 elems)
#define B_STR 272        // bytes per B row (136 elems)
#define ASZ   10240
#define BOFF  20480
#define BSZ   8704
#define SBUF  37888
#define SMEM_DYN (2 * SBUF)   // 75776

// ---------------- device scratch ----------------
__device__ int   g_cnt[NEXP];
__device__ int   g_tok[NEXP * TOK_MAX];
__device__ float g_wt [NEXP * TOK_MAX];
__device__ __align__(16) __nv_bfloat16 g_x_hi [(size_t)TOK_MAX * DIM];
__device__ __align__(16) __nv_bfloat16 g_x_lo [(size_t)TOK_MAX * DIM];
__device__ __align__(16) __nv_bfloat16 g_w1_hi[(size_t)NEXP * DIM * HID];   // [e][k=D][n=H]
__device__ __align__(16) __nv_bfloat16 g_w1_lo[(size_t)NEXP * DIM * HID];
__device__ __align__(16) __nv_bfloat16 g_w2_hi[(size_t)NEXP * HID * DIM];   // [e][k=H][n=D]
__device__ __align__(16) __nv_bfloat16 g_w2_lo[(size_t)NEXP * HID * DIM];
__device__ __align__(16) __nv_bfloat16 g_h_hi [(size_t)NEXP * TOK_MAX * HID];
__device__ __align__(16) __nv_bfloat16 g_h_lo [(size_t)NEXP * TOK_MAX * HID];

// ---------------- helpers ----------------
__device__ __forceinline__ uint32_t smem_u32(const void* p) {
    return (uint32_t)__cvta_generic_to_shared(p);
}
__device__ __forceinline__ void cp16(uint32_t dst, const void* src) {
    asm volatile("cp.async.cg.shared.global [%0], [%1], 16;"
                 :: "r"(dst), "l"(src) : "memory");
}
__device__ __forceinline__ void cp_commit() {
    asm volatile("cp.async.commit_group;" ::: "memory");
}
__device__ __forceinline__ void cp_wait0() {
    asm volatile("cp.async.wait_group 0;" ::: "memory");
}

#define LDSM_X4(r, addr) \
    asm volatile("ldmatrix.sync.aligned.m8n8.x4.shared.b16 {%0,%1,%2,%3}, [%4];" \
                 : "=r"((r)[0]), "=r"((r)[1]), "=r"((r)[2]), "=r"((r)[3]) : "r"(addr))
#define LDSM_X2T(r, addr) \
    asm volatile("ldmatrix.sync.aligned.m8n8.x2.trans.shared.b16 {%0,%1}, [%2];" \
                 : "=r"((r)[0]), "=r"((r)[1]) : "r"(addr))
#define MMA_BF16(d, a, b) \
    asm volatile("mma.sync.aligned.m16n8k16.row.col.f32.bf16.bf16.f32 " \
                 "{%0,%1,%2,%3},{%4,%5,%6,%7},{%8,%9},{%0,%1,%2,%3};" \
                 : "+f"((d)[0]), "+f"((d)[1]), "+f"((d)[2]), "+f"((d)[3]) \
                 : "r"((a)[0]), "r"((a)[1]), "r"((a)[2]), "r"((a)[3]), \
                   "r"((b)[0]), "r"((b)[1]))

__device__ __forceinline__ uint32_t pack2(__nv_bfloat16 a, __nv_bfloat16 b) {
    return (uint32_t)__bfloat16_as_ushort(a) | ((uint32_t)__bfloat16_as_ushort(b) << 16);
}
__device__ __forceinline__ void split_bf16(float v, __nv_bfloat16& h, __nv_bfloat16& l) {
    h = __float2bfloat16(v);
    l = __float2bfloat16(v - __bfloat162float(h));
}

// ---------------- reset ----------------
__global__ void reset_cnt_kernel() {
    if (threadIdx.x < NEXP) g_cnt[threadIdx.x] = 0;
}

// ---------------- router ----------------
__global__ void router_kernel(const float* __restrict__ x,
                              const float* __restrict__ Wr) {
    const int t   = blockIdx.x;
    const int tid = threadIdx.x;
    float acc0 = 0.f, acc1 = 0.f, acc2 = 0.f, acc3 = 0.f;
    const float4* wr4 = (const float4*)Wr;
    const float*  xr  = x + (size_t)t * DIM;
    for (int d = tid; d < DIM; d += 128) {
        float xv = xr[d];
        float4 w = wr4[d];
        acc0 = fmaf(xv, w.x, acc0);
        acc1 = fmaf(xv, w.y, acc1);
        acc2 = fmaf(xv, w.z, acc2);
        acc3 = fmaf(xv, w.w, acc3);
    }
    __shared__ float sr[4][128];
    sr[0][tid] = acc0; sr[1][tid] = acc1; sr[2][tid] = acc2; sr[3][tid] = acc3;
    __syncthreads();
    for (int s = 64; s > 0; s >>= 1) {
        if (tid < s) {
            sr[0][tid] += sr[0][tid + s];
            sr[1][tid] += sr[1][tid + s];
            sr[2][tid] += sr[2][tid + s];
            sr[3][tid] += sr[3][tid + s];
        }
        __syncthreads();
    }
    if (tid == 0) {
        float l[4] = { sr[0][0], sr[1][0], sr[2][0], sr[3][0] };
        int i0 = 0;
        #pragma unroll
        for (int e = 1; e < 4; e++) if (l[e] > l[i0]) i0 = e;
        int i1 = -1;
        #pragma unroll
        for (int e = 0; e < 4; e++) {
            if (e == i0) continue;
            if (i1 < 0 || l[e] > l[i1]) i1 = e;
        }
        float e1 = expf(l[i1] - l[i0]);
        float w0 = 1.0f / (1.0f + e1);
        float w1 = e1 / (1.0f + e1);
        int s0 = atomicAdd(&g_cnt[i0], 1);
        g_tok[i0 * TOK_MAX + s0] = t;
        g_wt [i0 * TOK_MAX + s0] = w0;
        int s1 = atomicAdd(&g_cnt[i1], 1);
        g_tok[i1 * TOK_MAX + s1] = t;
        g_wt [i1 * TOK_MAX + s1] = w1;
    }
}

// ---------------- elementwise split fp32 -> bf16 hi/lo ----------------
// which: 0 -> g_x, 1 -> g_w1, 2 -> g_w2.  Destination globals are resolved in
// DEVICE code (passing __device__ symbols as host-side kernel args gives the
// host shadow address, which ATS silently accepts on GB300 -> R3 bug).
__global__ void conv_split_kernel(const float* __restrict__ src, int which, int n4) {
    __nv_bfloat16* hi;
    __nv_bfloat16* lo;
    if (which == 0)      { hi = g_x_hi;  lo = g_x_lo;  }
    else if (which == 1) { hi = g_w1_hi; lo = g_w1_lo; }
    else                 { hi = g_w2_hi; lo = g_w2_lo; }
    int i = blockIdx.x * blockDim.x + threadIdx.x;
    if (i < n4) {
        float4 v = ((const float4*)src)[i];
        __nv_bfloat16 h0, l0, h1, l1, h2, l2, h3, l3;
        split_bf16(v.x, h0, l0);
        split_bf16(v.y, h1, l1);
        split_bf16(v.z, h2, l2);
        split_bf16(v.w, h3, l3);
        ((uint2*)hi)[i] = make_uint2(pack2(h0, h1), pack2(h2, h3));
        ((uint2*)lo)[i] = make_uint2(pack2(l0, l1), pack2(l2, l3));
    }
}

// ---------------- GEMM1: h = relu(Xg @ W1_e + b1_e), mma.sync bf16x3 ----------------
__global__ void __launch_bounds__(256, 1)
gemm1_mma(const float* __restrict__ b1) {
    extern __shared__ __align__(16) char smem[];
    const int e   = blockIdx.z;
    const int cnt = g_cnt[e];
    const int m0  = blockIdx.x * TM;
    if (m0 >= cnt) return;
    const int n0  = blockIdx.y * TN;
    const int t    = threadIdx.x;
    const int wid  = t >> 5;
    const int lane = t & 31;
    const int wm0  = (wid >> 2) * 64;
    const int wn0  = (wid & 3) * 32;
    const uint32_t sbase = smem_u32(smem);

    // global->smem mappings
    const int ar = t >> 1;
    const int slotA = m0 + ar;
    const int tokA = g_tok[e * TOK_MAX + (slotA < cnt ? slotA : 0)];
    const size_t   aOff = (size_t)tokA * DIM + (t & 1) * 16;
    const uint32_t aDst = (uint32_t)(ar * A_STR + (t & 1) * 32);
    const int br = t >> 3, bseg = t & 7;
    const size_t   bOff = ((size_t)e * DIM + br) * HID + n0 + bseg * 16;
    const uint32_t bDst = (uint32_t)(BOFF + br * B_STR + bseg * 32);

    auto load_chunk = [&](int buf, int k0) {
        uint32_t bb = sbase + buf * SBUF;
        const __nv_bfloat16* ah = g_x_hi + aOff + k0;
        const __nv_bfloat16* al = g_x_lo + aOff + k0;
        cp16(bb + aDst,            ah);
        cp16(bb + aDst + 16,       ah + 8);
        cp16(bb + ASZ + aDst,      al);
        cp16(bb + ASZ + aDst + 16, al + 8);
        const __nv_bfloat16* bh = g_w1_hi + bOff + (size_t)k0 * HID;
        const __nv_bfloat16* bl = g_w1_lo + bOff + (size_t)k0 * HID;
        cp16(bb + bDst,            bh);
        cp16(bb + bDst + 16,       bh + 8);
        cp16(bb + BSZ + bDst,      bl);
        cp16(bb + BSZ + bDst + 16, bl + 8);
    };

    float d[4][4][4];
    #pragma unroll
    for (int i = 0; i < 4; i++)
        #pragma unroll
        for (int j = 0; j < 4; j++)
            #pragma unroll
            for (int q = 0; q < 4; q++) d[i][j][q] = 0.f;

    const uint32_t aFrag = (wm0 + (lane & 15)) * A_STR + (lane >> 4) * 16;
    const uint32_t bFrag = (lane & 15) * B_STR + wn0 * 2;

    load_chunk(0, 0);
    cp_commit();
    cp_wait0();
    __syncthreads();

    const int NC = DIM / TK;   // 32
    for (int ch = 0; ch < NC; ch++) {
        int buf = ch & 1;
        if (ch + 1 < NC) { load_chunk(buf ^ 1, (ch + 1) * TK); cp_commit(); }

        uint32_t Ab = sbase + buf * SBUF + aFrag;
        uint32_t Bb = sbase + buf * SBUF + BOFF + bFrag;
        #pragma unroll
        for (int ks = 0; ks < 2; ks++) {
            uint32_t ah[4][4], al[4][4];
            #pragma unroll
            for (int mi = 0; mi < 4; mi++) {
                LDSM_X4(ah[mi], Ab + mi * 16 * A_STR + ks * 32);
                LDSM_X4(al[mi], Ab + mi * 16 * A_STR + ks * 32 + ASZ);
            }
            #pragma unroll
            for (int ni = 0; ni < 4; ni++) {
                uint32_t bh[2], bl[2];
                LDSM_X2T(bh, Bb + ks * 16 * B_STR + ni * 16);
                LDSM_X2T(bl, Bb + ks * 16 * B_STR + ni * 16 + BSZ);
                #pragma unroll
                for (int mi = 0; mi < 4; mi++) {
                    MMA_BF16(d[mi][ni], ah[mi], bh);
                    MMA_BF16(d[mi][ni], ah[mi], bl);
                    MMA_BF16(d[mi][ni], al[mi], bh);
                }
            }
        }
        if (ch + 1 < NC) { cp_wait0(); __syncthreads(); }
    }

    // epilogue: bias + relu -> bf16 hi/lo
    const int trow = lane >> 2;
    const int tcol = 2 * (lane & 3);
    #pragma unroll
    for (int mi = 0; mi < 4; mi++) {
        #pragma unroll
        for (int h2 = 0; h2 < 2; h2++) {
            int row  = wm0 + mi * 16 + trow + h2 * 8;
            int slot = m0 + row;
            if (slot < cnt) {
                size_t hb = ((size_t)e * TOK_MAX + slot) * HID;
                #pragma unroll
                for (int ni = 0; ni < 4; ni++) {
                    int col = n0 + wn0 + ni * 8 + tcol;
                    float v0 = fmaxf(d[mi][ni][h2 * 2 + 0] + __ldg(&b1[e * HID + col]),     0.f);
                    float v1 = fmaxf(d[mi][ni][h2 * 2 + 1] + __ldg(&b1[e * HID + col + 1]), 0.f);
                    __nv_bfloat16 h0, l0, h1, l1;
                    split_bf16(v0, h0, l0);
                    split_bf16(v1, h1, l1);
                    *(uint32_t*)(g_h_hi + hb + col) = pack2(h0, h1);
                    *(uint32_t*)(g_h_lo + hb + col) = pack2(l0, l1);
                }
            }
        }
    }
}

// ---------------- GEMM2: out[tok] += w*(h @ W2_e + b2_e), mma.sync bf16x3 ----------------
__global__ void __launch_bounds__(256, 1)
gemm2_mma(const float* __restrict__ b2, float* __restrict__ out) {
    extern __shared__ __align__(16) char smem[];
    const int e   = blockIdx.z;
    const int cnt = g_cnt[e];
    const int m0  = blockIdx.x * TM;
    if (m0 >= cnt) return;
    const int n0  = blockIdx.y * TN;
    const int t    = threadIdx.x;
    const int wid  = t >> 5;
    const int lane = t & 31;
    const int wm0  = (wid >> 2) * 64;
    const int wn0  = (wid & 3) * 32;
    const uint32_t sbase = smem_u32(smem);

    const int ar = t >> 1;
    const size_t   aOff = ((size_t)e * TOK_MAX + m0 + ar) * HID + (t & 1) * 16;
    const uint32_t aDst = (uint32_t)(ar * A_STR + (t & 1) * 32);
    const int br = t >> 3, bseg = t & 7;
    const size_t   bOff = ((size_t)e * HID + br) * DIM + n0 + bseg * 16;
    const uint32_t bDst = (uint32_t)(BOFF + br * B_STR + bseg * 32);

    auto load_chunk = [&](int buf, int k0) {
        uint32_t bb = sbase + buf * SBUF;
        const __nv_bfloat16* ah = g_h_hi + aOff + k0;
        const __nv_bfloat16* al = g_h_lo + aOff + k0;
        cp16(bb + aDst,            ah);
        cp16(bb + aDst + 16,       ah + 8);
        cp16(bb + ASZ + aDst,      al);
        cp16(bb + ASZ + aDst + 16, al + 8);
        const __nv_bfloat16* bh = g_w2_hi + bOff + (size_t)k0 * DIM;
        const __nv_bfloat16* bl = g_w2_lo + bOff + (size_t)k0 * DIM;
        cp16(bb + bDst,            bh);
        cp16(bb + bDst + 16,       bh + 8);
        cp16(bb + BSZ + bDst,      bl);
        cp16(bb + BSZ + bDst + 16, bl + 8);
    };

    float d[4][4][4];
    #pragma unroll
    for (int i = 0; i < 4; i++)
        #pragma unroll
        for (int j = 0; j < 4; j++)
            #pragma unroll
            for (int q = 0; q < 4; q++) d[i][j][q] = 0.f;

    const uint32_t aFrag = (wm0 + (lane & 15)) * A_STR + (lane >> 4) * 16;
    const uint32_t bFrag = (lane & 15) * B_STR + wn0 * 2;

    load_chunk(0, 0);
    cp_commit();
    cp_wait0();
    __syncthreads();

    const int NC = HID / TK;   // 128
    for (int ch = 0; ch < NC; ch++) {
        int buf = ch & 1;
        if (ch + 1 < NC) { load_chunk(buf ^ 1, (ch + 1) * TK); cp_commit(); }

        uint32_t Ab = sbase + buf * SBUF + aFrag;
        uint32_t Bb = sbase + buf * SBUF + BOFF + bFrag;
        #pragma unroll
        for (int ks = 0; ks < 2; ks++) {
            uint32_t ah[4][4], al[4][4];
            #pragma unroll
            for (int mi = 0; mi < 4; mi++) {
                LDSM_X4(ah[mi], Ab + mi * 16 * A_STR + ks * 32);
                LDSM_X4(al[mi], Ab + mi * 16 * A_STR + ks * 32 + ASZ);
            }
            #pragma unroll
            for (int ni = 0; ni < 4; ni++) {
                uint32_t bh[2], bl[2];
                LDSM_X2T(bh, Bb + ks * 16 * B_STR + ni * 16);
                LDSM_X2T(bl, Bb + ks * 16 * B_STR + ni * 16 + BSZ);
                #pragma unroll
                for (int mi = 0; mi < 4; mi++) {
                    MMA_BF16(d[mi][ni], ah[mi], bh);
                    MMA_BF16(d[mi][ni], ah[mi], bl);
                    MMA_BF16(d[mi][ni], al[mi], bh);
                }
            }
        }
        if (ch + 1 < NC) { cp_wait0(); __syncthreads(); }
    }

    // epilogue: wt*(acc + b2) -> atomicAdd into out
    const int trow = lane >> 2;
    const int tcol = 2 * (lane & 3);
    #pragma unroll
    for (int mi = 0; mi < 4; mi++) {
        #pragma unroll
        for (int h2 = 0; h2 < 2; h2++) {
            int row  = wm0 + mi * 16 + trow + h2 * 8;
            int slot = m0 + row;
            if (slot < cnt) {
                int   tok = g_tok[e * TOK_MAX + slot];
                float wt  = g_wt [e * TOK_MAX + slot];
                float* orow = out + (size_t)tok * DIM;
                #pragma unroll
                for (int ni = 0; ni < 4; ni++) {
                    int col = n0 + wn0 + ni * 8 + tcol;
                    atomicAdd(orow + col,     wt * (d[mi][ni][h2 * 2 + 0] + __ldg(&b2[e * DIM + col])));
                    atomicAdd(orow + col + 1, wt * (d[mi][ni][h2 * 2 + 1] + __ldg(&b2[e * DIM + col + 1])));
                }
            }
        }
    }
}

// ---------------- launch ----------------
extern "C" void kernel_launch(void* const* d_in, const int* in_sizes, int n_in,
                              void* d_out, int out_size) {
    const float* x  = (const float*)d_in[0];
    const float* Wr = (const float*)d_in[1];
    const float* W1 = (const float*)d_in[2];
    const float* b1 = (const float*)d_in[3];
    const float* W2 = (const float*)d_in[4];
    const float* b2 = (const float*)d_in[5];
    float* out = (float*)d_out;

    const int T = in_sizes[0] / DIM;   // 8192 tokens

    cudaFuncSetAttribute(gemm1_mma, cudaFuncAttributeMaxDynamicSharedMemorySize, SMEM_DYN);
    cudaFuncSetAttribute(gemm2_mma, cudaFuncAttributeMaxDynamicSharedMemorySize, SMEM_DYN);

    cudaMemsetAsync(out, 0, (size_t)out_size * sizeof(float));

    reset_cnt_kernel<<<1, 32>>>();
    router_kernel<<<T, 128>>>(x, Wr);

    // conversions (destinations resolved device-side via `which`)
    {
        int nx = T * DIM / 4;
        conv_split_kernel<<<(nx + 255) / 256, 256>>>(x, 0, nx);
        int nw = NEXP * DIM * HID / 4;
        conv_split_kernel<<<(nw + 255) / 256, 256>>>(W1, 1, nw);
        conv_split_kernel<<<(nw + 255) / 256, 256>>>(W2, 2, nw);
    }

    dim3 gg1(TOK_MAX / TM, HID / TN, NEXP);
    gemm1_mma<<<gg1, 256, SMEM_DYN>>>(b1);

    dim3 gg2(TOK_MAX / TM, DIM / TN, NEXP);
    gemm2_mma<<<gg2, 256, SMEM_DYN>>>(b2, out);
}

// round 5
// speedup vs baseline: 4.8726x; 2.0063x over previous
#include <cuda_runtime.h>
#include <cuda_fp16.h>
#include <math.h>
#include <stdint.h>

// Problem constants (MixtureOfExperts_67010079752265)
#define TOK_MAX 8192
#define DIM     1024
#define NEXP    4
#define HID     4096

// GEMM tiling (mma.sync m16n8k16 fp16, fp32 accum)
#define TM 128
#define TN 256
#define TK 64
#define A_STR 144                 // bytes per A smem row (64 halfs + 8 pad)
#define ASZ   (128 * 144)         // 18432
#define BOFF  ASZ
#define B_STR 528                 // bytes per B smem row (256 halfs + 8 pad)
#define BSZ   (64 * 528)          // 33792
#define SBUF  (ASZ + BSZ)         // 52224
#define SMEM_DYN (2 * SBUF)       // 104448

// ---------------- device scratch ----------------
__device__ int   g_cnt[NEXP];
__device__ int   g_tok[NEXP * TOK_MAX];
__device__ float g_wt [NEXP * TOK_MAX];
__device__ __align__(16) __half g_x_h [(size_t)TOK_MAX * DIM];
__device__ __align__(16) __half g_w1_h[(size_t)NEXP * DIM * HID];   // [e][k=D][n=H]
__device__ __align__(16) __half g_w2_h[(size_t)NEXP * HID * DIM];   // [e][k=H][n=D]
__device__ __align__(16) __half g_h_h [(size_t)NEXP * TOK_MAX * HID];

// ---------------- helpers ----------------
__device__ __forceinline__ uint32_t smem_u32(const void* p) {
    return (uint32_t)__cvta_generic_to_shared(p);
}
__device__ __forceinline__ void cp16(uint32_t dst, const void* src) {
    asm volatile("cp.async.cg.shared.global [%0], [%1], 16;"
                 :: "r"(dst), "l"(src) : "memory");
}
__device__ __forceinline__ void cp_commit() {
    asm volatile("cp.async.commit_group;" ::: "memory");
}
__device__ __forceinline__ void cp_wait0() {
    asm volatile("cp.async.wait_group 0;" ::: "memory");
}

#define LDSM_X4(r, addr) \
    asm volatile("ldmatrix.sync.aligned.m8n8.x4.shared.b16 {%0,%1,%2,%3}, [%4];" \
                 : "=r"((r)[0]), "=r"((r)[1]), "=r"((r)[2]), "=r"((r)[3]) : "r"(addr))
#define LDSM_X4T(r, addr) \
    asm volatile("ldmatrix.sync.aligned.m8n8.x4.trans.shared.b16 {%0,%1,%2,%3}, [%4];" \
                 : "=r"((r)[0]), "=r"((r)[1]), "=r"((r)[2]), "=r"((r)[3]) : "r"(addr))
#define MMA_F16(d, a, b0, b1) \
    asm volatile("mma.sync.aligned.m16n8k16.row.col.f32.f16.f16.f32 " \
                 "{%0,%1,%2,%3},{%4,%5,%6,%7},{%8,%9},{%0,%1,%2,%3};" \
                 : "+f"((d)[0]), "+f"((d)[1]), "+f"((d)[2]), "+f"((d)[3]) \
                 : "r"((a)[0]), "r"((a)[1]), "r"((a)[2]), "r"((a)[3]), \
                   "r"(b0), "r"(b1))

__device__ __forceinline__ uint32_t pack2h(__half a, __half b) {
    return (uint32_t)__half_as_ushort(a) | ((uint32_t)__half_as_ushort(b) << 16);
}

// ---------------- reset ----------------
__global__ void reset_cnt_kernel() {
    if (threadIdx.x < NEXP) g_cnt[threadIdx.x] = 0;
}

// ---------------- router ----------------
__global__ void router_kernel(const float* __restrict__ x,
                              const float* __restrict__ Wr) {
    const int t   = blockIdx.x;
    const int tid = threadIdx.x;
    float acc0 = 0.f, acc1 = 0.f, acc2 = 0.f, acc3 = 0.f;
    const float4* wr4 = (const float4*)Wr;
    const float*  xr  = x + (size_t)t * DIM;
    for (int d = tid; d < DIM; d += 128) {
        float xv = xr[d];
        float4 w = wr4[d];
        acc0 = fmaf(xv, w.x, acc0);
        acc1 = fmaf(xv, w.y, acc1);
        acc2 = fmaf(xv, w.z, acc2);
        acc3 = fmaf(xv, w.w, acc3);
    }
    __shared__ float sr[4][128];
    sr[0][tid] = acc0; sr[1][tid] = acc1; sr[2][tid] = acc2; sr[3][tid] = acc3;
    __syncthreads();
    for (int s = 64; s > 0; s >>= 1) {
        if (tid < s) {
            sr[0][tid] += sr[0][tid + s];
            sr[1][tid] += sr[1][tid + s];
            sr[2][tid] += sr[2][tid + s];
            sr[3][tid] += sr[3][tid + s];
        }
        __syncthreads();
    }
    if (tid == 0) {
        float l[4] = { sr[0][0], sr[1][0], sr[2][0], sr[3][0] };
        int i0 = 0;
        #pragma unroll
        for (int e = 1; e < 4; e++) if (l[e] > l[i0]) i0 = e;
        int i1 = -1;
        #pragma unroll
        for (int e = 0; e < 4; e++) {
            if (e == i0) continue;
            if (i1 < 0 || l[e] > l[i1]) i1 = e;
        }
        float e1 = expf(l[i1] - l[i0]);
        float w0 = 1.0f / (1.0f + e1);
        float w1 = e1 / (1.0f + e1);
        int s0 = atomicAdd(&g_cnt[i0], 1);
        g_tok[i0 * TOK_MAX + s0] = t;
        g_wt [i0 * TOK_MAX + s0] = w0;
        int s1 = atomicAdd(&g_cnt[i1], 1);
        g_tok[i1 * TOK_MAX + s1] = t;
        g_wt [i1 * TOK_MAX + s1] = w1;
    }
}

// ---------------- fp32 -> fp16 conversion ----------------
// which: 0 -> g_x_h, 1 -> g_w1_h, 2 -> g_w2_h (resolved device-side; see R3 bug)
__global__ void conv_f16_kernel(const float* __restrict__ src, int which, int n4) {
    __half* dst;
    if (which == 0)      dst = g_x_h;
    else if (which == 1) dst = g_w1_h;
    else                 dst = g_w2_h;
    int i = blockIdx.x * blockDim.x + threadIdx.x;
    if (i < n4) {
        float4 v = ((const float4*)src)[i];
        ((uint2*)dst)[i] = make_uint2(pack2h(__float2half(v.x), __float2half(v.y)),
                                      pack2h(__float2half(v.z), __float2half(v.w)));
    }
}

// ---------------- GEMM1: h = relu(Xg @ W1_e + b1_e), fp16 mma ----------------
__global__ void __launch_bounds__(256)
gemm1_mma(const float* __restrict__ b1) {
    extern __shared__ __align__(16) char smem[];
    const int e   = blockIdx.z;
    const int cnt = g_cnt[e];
    const int m0  = blockIdx.x * TM;
    if (m0 >= cnt) return;
    const int n0  = blockIdx.y * TN;
    const int t    = threadIdx.x;
    const int wid  = t >> 5;
    const int lane = t & 31;
    const int wm0  = (wid >> 2) * 64;
    const int wn0  = (wid & 3) * 64;
    const uint32_t sbase = smem_u32(smem);

    // A gmem->smem: thread -> row t>>1, 4 cp16 (64B)
    const int arow = t >> 1;
    const int aseg = t & 1;
    const int slotA = m0 + arow;
    const int tokA = g_tok[e * TOK_MAX + (slotA < cnt ? slotA : 0)];
    const size_t   aOff = (size_t)tokA * DIM + aseg * 32;
    const uint32_t aDst = (uint32_t)(arow * A_STR + aseg * 64);
    // B gmem->smem: thread -> row t>>2, 8 cp16 (128B)
    const int brow = t >> 2;
    const int bseg = t & 3;
    const size_t   bOff = ((size_t)e * DIM + brow) * HID + n0 + bseg * 64;
    const uint32_t bDst = (uint32_t)(BOFF + brow * B_STR + bseg * 128);

    auto load_chunk = [&](int buf, int k0) {
        uint32_t bb = sbase + buf * SBUF;
        const __half* ap = g_x_h + aOff + k0;
        #pragma unroll
        for (int i = 0; i < 4; i++) cp16(bb + aDst + i * 16, ap + i * 8);
        const __half* bp = g_w1_h + bOff + (size_t)k0 * HID;
        #pragma unroll
        for (int i = 0; i < 8; i++) cp16(bb + bDst + i * 16, bp + i * 8);
    };

    float d[4][8][4];
    #pragma unroll
    for (int i = 0; i < 4; i++)
        #pragma unroll
        for (int j = 0; j < 8; j++)
            #pragma unroll
            for (int q = 0; q < 4; q++) d[i][j][q] = 0.f;

    const uint32_t aFrag = (wm0 + (lane & 15)) * A_STR + (lane >> 4) * 16;
    const uint32_t bFrag = (lane & 15) * B_STR + wn0 * 2 + (lane >> 4) * 16;

    load_chunk(0, 0);
    cp_commit();
    cp_wait0();
    __syncthreads();

    const int NC = DIM / TK;   // 16
    for (int ch = 0; ch < NC; ch++) {
        int buf = ch & 1;
        if (ch + 1 < NC) { load_chunk(buf ^ 1, (ch + 1) * TK); cp_commit(); }

        uint32_t Ab = sbase + buf * SBUF + aFrag;
        uint32_t Bb = sbase + buf * SBUF + BOFF + bFrag;
        #pragma unroll
        for (int ks = 0; ks < 4; ks++) {
            uint32_t a[4][4];
            #pragma unroll
            for (int mi = 0; mi < 4; mi++)
                LDSM_X4(a[mi], Ab + mi * 16 * A_STR + ks * 32);
            #pragma unroll
            for (int nj = 0; nj < 4; nj++) {
                uint32_t b[4];
                LDSM_X4T(b, Bb + ks * 16 * B_STR + nj * 32);
                #pragma unroll
                for (int mi = 0; mi < 4; mi++) {
                    MMA_F16(d[mi][2 * nj],     a[mi], b[0], b[1]);
                    MMA_F16(d[mi][2 * nj + 1], a[mi], b[2], b[3]);
                }
            }
        }
        if (ch + 1 < NC) { cp_wait0(); __syncthreads(); }
    }

    // epilogue: bias + relu -> fp16 h (indexed by slot)
    const int trow = lane >> 2;
    const int tcol = 2 * (lane & 3);
    #pragma unroll
    for (int mi = 0; mi < 4; mi++) {
        #pragma unroll
        for (int h2 = 0; h2 < 2; h2++) {
            int slot = m0 + wm0 + mi * 16 + trow + h2 * 8;
            if (slot < cnt) {
                size_t hb = ((size_t)e * TOK_MAX + slot) * HID;
                #pragma unroll
                for (int ni = 0; ni < 8; ni++) {
                    int col = n0 + wn0 + ni * 8 + tcol;
                    float v0 = fmaxf(d[mi][ni][h2 * 2 + 0] + __ldg(&b1[e * HID + col]),     0.f);
                    float v1 = fmaxf(d[mi][ni][h2 * 2 + 1] + __ldg(&b1[e * HID + col + 1]), 0.f);
                    *(uint32_t*)(g_h_h + hb + col) = pack2h(__float2half(v0), __float2half(v1));
                }
            }
        }
    }
}

// ---------------- GEMM2: out[tok] += w*(h @ W2_e + b2_e), fp16 mma ----------------
__global__ void __launch_bounds__(256)
gemm2_mma(const float* __restrict__ b2, float* __restrict__ out) {
    extern __shared__ __align__(16) char smem[];
    const int e   = blockIdx.z;
    const int cnt = g_cnt[e];
    const int m0  = blockIdx.x * TM;
    if (m0 >= cnt) return;
    const int n0  = blockIdx.y * TN;
    const int t    = threadIdx.x;
    const int wid  = t >> 5;
    const int lane = t & 31;
    const int wm0  = (wid >> 2) * 64;
    const int wn0  = (wid & 3) * 64;
    const uint32_t sbase = smem_u32(smem);

    const int arow = t >> 1;
    const int aseg = t & 1;
    const size_t   aOff = ((size_t)e * TOK_MAX + m0 + arow) * HID + aseg * 32;
    const uint32_t aDst = (uint32_t)(arow * A_STR + aseg * 64);
    const int brow = t >> 2;
    const int bseg = t & 3;
    const size_t   bOff = ((size_t)e * HID + brow) * DIM + n0 + bseg * 64;
    const uint32_t bDst = (uint32_t)(BOFF + brow * B_STR + bseg * 128);

    auto load_chunk = [&](int buf, int k0) {
        uint32_t bb = sbase + buf * SBUF;
        const __half* ap = g_h_h + aOff + k0;
        #pragma unroll
        for (int i = 0; i < 4; i++) cp16(bb + aDst + i * 16, ap + i * 8);
        const __half* bp = g_w2_h + bOff + (size_t)k0 * DIM;
        #pragma unroll
        for (int i = 0; i < 8; i++) cp16(bb + bDst + i * 16, bp + i * 8);
    };

    float d[4][8][4];
    #pragma unroll
    for (int i = 0; i < 4; i++)
        #pragma unroll
        for (int j = 0; j < 8; j++)
            #pragma unroll
            for (int q = 0; q < 4; q++) d[i][j][q] = 0.f;

    const uint32_t aFrag = (wm0 + (lane & 15)) * A_STR + (lane >> 4) * 16;
    const uint32_t bFrag = (lane & 15) * B_STR + wn0 * 2 + (lane >> 4) * 16;

    load_chunk(0, 0);
    cp_commit();
    cp_wait0();
    __syncthreads();

    const int NC = HID / TK;   // 64
    for (int ch = 0; ch < NC; ch++) {
        int buf = ch & 1;
        if (ch + 1 < NC) { load_chunk(buf ^ 1, (ch + 1) * TK); cp_commit(); }

        uint32_t Ab = sbase + buf * SBUF + aFrag;
        uint32_t Bb = sbase + buf * SBUF + BOFF + bFrag;
        #pragma unroll
        for (int ks = 0; ks < 4; ks++) {
            uint32_t a[4][4];
            #pragma unroll
            for (int mi = 0; mi < 4; mi++)
                LDSM_X4(a[mi], Ab + mi * 16 * A_STR + ks * 32);
            #pragma unroll
            for (int nj = 0; nj < 4; nj++) {
                uint32_t b[4];
                LDSM_X4T(b, Bb + ks * 16 * B_STR + nj * 32);
                #pragma unroll
                for (int mi = 0; mi < 4; mi++) {
                    MMA_F16(d[mi][2 * nj],     a[mi], b[0], b[1]);
                    MMA_F16(d[mi][2 * nj + 1], a[mi], b[2], b[3]);
                }
            }
        }
        if (ch + 1 < NC) { cp_wait0(); __syncthreads(); }
    }

    // epilogue: wt*(acc + b2) -> atomicAdd into out
    const int trow = lane >> 2;
    const int tcol = 2 * (lane & 3);
    #pragma unroll
    for (int mi = 0; mi < 4; mi++) {
        #pragma unroll
        for (int h2 = 0; h2 < 2; h2++) {
            int slot = m0 + wm0 + mi * 16 + trow + h2 * 8;
            if (slot < cnt) {
                int   tok = g_tok[e * TOK_MAX + slot];
                float wt  = g_wt [e * TOK_MAX + slot];
                float* orow = out + (size_t)tok * DIM;
                #pragma unroll
                for (int ni = 0; ni < 8; ni++) {
                    int col = n0 + wn0 + ni * 8 + tcol;
                    atomicAdd(orow + col,     wt * (d[mi][ni][h2 * 2 + 0] + __ldg(&b2[e * DIM + col])));
                    atomicAdd(orow + col + 1, wt * (d[mi][ni][h2 * 2 + 1] + __ldg(&b2[e * DIM + col + 1])));
                }
            }
        }
    }
}

// ---------------- launch ----------------
extern "C" void kernel_launch(void* const* d_in, const int* in_sizes, int n_in,
                              void* d_out, int out_size) {
    const float* x  = (const float*)d_in[0];
    const float* Wr = (const float*)d_in[1];
    const float* W1 = (const float*)d_in[2];
    const float* b1 = (const float*)d_in[3];
    const float* W2 = (const float*)d_in[4];
    const float* b2 = (const float*)d_in[5];
    float* out = (float*)d_out;

    const int T = in_sizes[0] / DIM;   // 8192 tokens

    cudaFuncSetAttribute(gemm1_mma, cudaFuncAttributeMaxDynamicSharedMemorySize, SMEM_DYN);
    cudaFuncSetAttribute(gemm2_mma, cudaFuncAttributeMaxDynamicSharedMemorySize, SMEM_DYN);

    cudaMemsetAsync(out, 0, (size_t)out_size * sizeof(float));

    reset_cnt_kernel<<<1, 32>>>();
    router_kernel<<<T, 128>>>(x, Wr);

    {
        int nx = T * DIM / 4;
        conv_f16_kernel<<<(nx + 255) / 256, 256>>>(x, 0, nx);
        int nw = NEXP * DIM * HID / 4;
        conv_f16_kernel<<<(nw + 255) / 256, 256>>>(W1, 1, nw);
        conv_f16_kernel<<<(nw + 255) / 256, 256>>>(W2, 2, nw);
    }

    dim3 gg1(TOK_MAX / TM, HID / TN, NEXP);   // (64, 16, 4)
    gemm1_mma<<<gg1, 256, SMEM_DYN>>>(b1);

    dim3 gg2(TOK_MAX / TM, DIM / TN, NEXP);   // (64, 4, 4)
    gemm2_mma<<<gg2, 256, SMEM_DYN>>>(b2, out);
}

// round 6
// speedup vs baseline: 5.8576x; 1.2022x over previous
#include <cuda_runtime.h>
#include <cuda_fp16.h>
#include <math.h>
#include <stdint.h>

// Problem constants (MixtureOfExperts_67010079752265)
#define TOK_MAX 8192
#define DIM     1024
#define NEXP    4
#define HID     4096

// GEMM tiling (mma.sync m16n8k16 fp16, fp32 accum)
#define TM 128
#define TN 256
#define TK 64
#define NTHR 512                  // 16 warps, warp tile 32x64
#define A_STR 144                 // bytes per A smem row (64 halfs + 8 pad)
#define ASZ   (128 * 144)         // 18432
#define BOFF  ASZ
#define B_STR 528                 // bytes per B smem row (256 halfs + 8 pad)
#define BSZ   (64 * 528)          // 33792
#define SBUF  (ASZ + BSZ)         // 52224
#define SMEM_DYN (2 * SBUF)       // 104448

// ---------------- device scratch ----------------
__device__ int   g_cnt[NEXP];
__device__ int   g_tok[NEXP * TOK_MAX];
__device__ float g_wt [NEXP * TOK_MAX];
__device__ __align__(16) __half g_x_h [(size_t)TOK_MAX * DIM];
__device__ __align__(16) __half g_w1_h[(size_t)NEXP * DIM * HID];   // [e][k=D][n=H]
__device__ __align__(16) __half g_w2_h[(size_t)NEXP * HID * DIM];   // [e][k=H][n=D]
__device__ __align__(16) __half g_h_h [(size_t)NEXP * TOK_MAX * HID];

// ---------------- helpers ----------------
__device__ __forceinline__ uint32_t smem_u32(const void* p) {
    return (uint32_t)__cvta_generic_to_shared(p);
}
__device__ __forceinline__ void cp16(uint32_t dst, const void* src) {
    asm volatile("cp.async.cg.shared.global [%0], [%1], 16;"
                 :: "r"(dst), "l"(src) : "memory");
}
__device__ __forceinline__ void cp_commit() {
    asm volatile("cp.async.commit_group;" ::: "memory");
}
__device__ __forceinline__ void cp_wait0() {
    asm volatile("cp.async.wait_group 0;" ::: "memory");
}

#define LDSM_X4(r, addr) \
    asm volatile("ldmatrix.sync.aligned.m8n8.x4.shared.b16 {%0,%1,%2,%3}, [%4];" \
                 : "=r"((r)[0]), "=r"((r)[1]), "=r"((r)[2]), "=r"((r)[3]) : "r"(addr))
#define LDSM_X4T(r, addr) \
    asm volatile("ldmatrix.sync.aligned.m8n8.x4.trans.shared.b16 {%0,%1,%2,%3}, [%4];" \
                 : "=r"((r)[0]), "=r"((r)[1]), "=r"((r)[2]), "=r"((r)[3]) : "r"(addr))
#define MMA_F16(d, a, b0, b1) \
    asm volatile("mma.sync.aligned.m16n8k16.row.col.f32.f16.f16.f32 " \
                 "{%0,%1,%2,%3},{%4,%5,%6,%7},{%8,%9},{%0,%1,%2,%3};" \
                 : "+f"((d)[0]), "+f"((d)[1]), "+f"((d)[2]), "+f"((d)[3]) \
                 : "r"((a)[0]), "r"((a)[1]), "r"((a)[2]), "r"((a)[3]), \
                   "r"(b0), "r"(b1))

__device__ __forceinline__ uint32_t pack2h(__half a, __half b) {
    return (uint32_t)__half_as_ushort(a) | ((uint32_t)__half_as_ushort(b) << 16);
}

// ---------------- reset ----------------
__global__ void reset_cnt_kernel() {
    if (threadIdx.x < NEXP) g_cnt[threadIdx.x] = 0;
}

// ---------------- router ----------------
__global__ void router_kernel(const float* __restrict__ x,
                              const float* __restrict__ Wr) {
    const int t   = blockIdx.x;
    const int tid = threadIdx.x;
    float acc0 = 0.f, acc1 = 0.f, acc2 = 0.f, acc3 = 0.f;
    const float4* wr4 = (const float4*)Wr;
    const float*  xr  = x + (size_t)t * DIM;
    for (int d = tid; d < DIM; d += 128) {
        float xv = xr[d];
        float4 w = wr4[d];
        acc0 = fmaf(xv, w.x, acc0);
        acc1 = fmaf(xv, w.y, acc1);
        acc2 = fmaf(xv, w.z, acc2);
        acc3 = fmaf(xv, w.w, acc3);
    }
    __shared__ float sr[4][128];
    sr[0][tid] = acc0; sr[1][tid] = acc1; sr[2][tid] = acc2; sr[3][tid] = acc3;
    __syncthreads();
    for (int s = 64; s > 0; s >>= 1) {
        if (tid < s) {
            sr[0][tid] += sr[0][tid + s];
            sr[1][tid] += sr[1][tid + s];
            sr[2][tid] += sr[2][tid + s];
            sr[3][tid] += sr[3][tid + s];
        }
        __syncthreads();
    }
    if (tid == 0) {
        float l[4] = { sr[0][0], sr[1][0], sr[2][0], sr[3][0] };
        int i0 = 0;
        #pragma unroll
        for (int e = 1; e < 4; e++) if (l[e] > l[i0]) i0 = e;
        int i1 = -1;
        #pragma unroll
        for (int e = 0; e < 4; e++) {
            if (e == i0) continue;
            if (i1 < 0 || l[e] > l[i1]) i1 = e;
        }
        float e1 = expf(l[i1] - l[i0]);
        float w0 = 1.0f / (1.0f + e1);
        float w1 = e1 / (1.0f + e1);
        int s0 = atomicAdd(&g_cnt[i0], 1);
        g_tok[i0 * TOK_MAX + s0] = t;
        g_wt [i0 * TOK_MAX + s0] = w0;
        int s1 = atomicAdd(&g_cnt[i1], 1);
        g_tok[i1 * TOK_MAX + s1] = t;
        g_wt [i1 * TOK_MAX + s1] = w1;
    }
}

// ---------------- fp32 -> fp16 conversion ----------------
// which: 0 -> g_x_h, 1 -> g_w1_h, 2 -> g_w2_h (resolved device-side; see R3 bug)
__global__ void conv_f16_kernel(const float* __restrict__ src, int which, int n4) {
    __half* dst;
    if (which == 0)      dst = g_x_h;
    else if (which == 1) dst = g_w1_h;
    else                 dst = g_w2_h;
    int i = blockIdx.x * blockDim.x + threadIdx.x;
    if (i < n4) {
        float4 v = ((const float4*)src)[i];
        ((uint2*)dst)[i] = make_uint2(pack2h(__float2half(v.x), __float2half(v.y)),
                                      pack2h(__float2half(v.z), __float2half(v.w)));
    }
}

// ---------------- GEMM1: h = relu(Xg @ W1_e + b1_e), fp16 mma ----------------
__global__ void __launch_bounds__(NTHR)
gemm1_mma(const float* __restrict__ b1) {
    extern __shared__ __align__(16) char smem[];
    const int e   = blockIdx.z;
    const int cnt = g_cnt[e];
    const int m0  = blockIdx.x * TM;
    if (m0 >= cnt) return;
    const int n0  = blockIdx.y * TN;
    const int t    = threadIdx.x;
    const int wid  = t >> 5;
    const int lane = t & 31;
    const int wm0  = (wid >> 2) * 32;   // 4 row groups of 32
    const int wn0  = (wid & 3) * 64;    // 4 col groups of 64
    const uint32_t sbase = smem_u32(smem);

    // A gmem->smem: 4 threads/row, 2 cp16 (32B) each
    const int arow = t >> 2;
    const int aseg = t & 3;
    const int slotA = m0 + arow;
    const int tokA = g_tok[e * TOK_MAX + (slotA < cnt ? slotA : 0)];
    const size_t   aOff = (size_t)tokA * DIM + aseg * 16;
    const uint32_t aDst = (uint32_t)(arow * A_STR + aseg * 32);
    // B gmem->smem: 8 threads/row, 4 cp16 (64B) each
    const int brow = t >> 3;
    const int bseg = t & 7;
    const size_t   bOff = ((size_t)e * DIM + brow) * HID + n0 + bseg * 32;
    const uint32_t bDst = (uint32_t)(BOFF + brow * B_STR + bseg * 64);

    auto load_chunk = [&](int buf, int k0) {
        uint32_t bb = sbase + buf * SBUF;
        const __half* ap = g_x_h + aOff + k0;
        #pragma unroll
        for (int i = 0; i < 2; i++) cp16(bb + aDst + i * 16, ap + i * 8);
        const __half* bp = g_w1_h + bOff + (size_t)k0 * HID;
        #pragma unroll
        for (int i = 0; i < 4; i++) cp16(bb + bDst + i * 16, bp + i * 8);
    };

    float d[2][8][4];
    #pragma unroll
    for (int i = 0; i < 2; i++)
        #pragma unroll
        for (int j = 0; j < 8; j++)
            #pragma unroll
            for (int q = 0; q < 4; q++) d[i][j][q] = 0.f;

    const uint32_t aFrag = (wm0 + (lane & 15)) * A_STR + (lane >> 4) * 16;
    const uint32_t bFrag = (lane & 15) * B_STR + wn0 * 2 + (lane >> 4) * 16;

    load_chunk(0, 0);
    cp_commit();
    cp_wait0();
    __syncthreads();

    const int NC = DIM / TK;   // 16
    for (int ch = 0; ch < NC; ch++) {
        int buf = ch & 1;
        if (ch + 1 < NC) { load_chunk(buf ^ 1, (ch + 1) * TK); cp_commit(); }

        uint32_t Ab = sbase + buf * SBUF + aFrag;
        uint32_t Bb = sbase + buf * SBUF + BOFF + bFrag;
        #pragma unroll
        for (int ks = 0; ks < 4; ks++) {
            uint32_t a[2][4];
            #pragma unroll
            for (int mi = 0; mi < 2; mi++)
                LDSM_X4(a[mi], Ab + mi * 16 * A_STR + ks * 32);
            #pragma unroll
            for (int nj = 0; nj < 4; nj++) {
                uint32_t b[4];
                LDSM_X4T(b, Bb + ks * 16 * B_STR + nj * 32);
                #pragma unroll
                for (int mi = 0; mi < 2; mi++) {
                    MMA_F16(d[mi][2 * nj],     a[mi], b[0], b[1]);
                    MMA_F16(d[mi][2 * nj + 1], a[mi], b[2], b[3]);
                }
            }
        }
        if (ch + 1 < NC) { cp_wait0(); __syncthreads(); }
    }

    // epilogue: bias + relu -> fp16 h (indexed by slot)
    const int trow = lane >> 2;
    const int tcol = 2 * (lane & 3);
    #pragma unroll
    for (int mi = 0; mi < 2; mi++) {
        #pragma unroll
        for (int h2 = 0; h2 < 2; h2++) {
            int slot = m0 + wm0 + mi * 16 + trow + h2 * 8;
            if (slot < cnt) {
                size_t hb = ((size_t)e * TOK_MAX + slot) * HID;
                #pragma unroll
                for (int ni = 0; ni < 8; ni++) {
                    int col = n0 + wn0 + ni * 8 + tcol;
                    float v0 = fmaxf(d[mi][ni][h2 * 2 + 0] + __ldg(&b1[e * HID + col]),     0.f);
                    float v1 = fmaxf(d[mi][ni][h2 * 2 + 1] + __ldg(&b1[e * HID + col + 1]), 0.f);
                    *(uint32_t*)(g_h_h + hb + col) = pack2h(__float2half(v0), __float2half(v1));
                }
            }
        }
    }
}

// ---------------- GEMM2: out[tok] += w*(h @ W2_e + b2_e), fp16 mma ----------------
__global__ void __launch_bounds__(NTHR)
gemm2_mma(const float* __restrict__ b2, float* __restrict__ out) {
    extern __shared__ __align__(16) char smem[];
    const int e   = blockIdx.z;
    const int cnt = g_cnt[e];
    const int m0  = blockIdx.x * TM;
    if (m0 >= cnt) return;
    const int n0  = blockIdx.y * TN;
    const int t    = threadIdx.x;
    const int wid  = t >> 5;
    const int lane = t & 31;
    const int wm0  = (wid >> 2) * 32;
    const int wn0  = (wid & 3) * 64;
    const uint32_t sbase = smem_u32(smem);

    const int arow = t >> 2;
    const int aseg = t & 3;
    const size_t   aOff = ((size_t)e * TOK_MAX + m0 + arow) * HID + aseg * 16;
    const uint32_t aDst = (uint32_t)(arow * A_STR + aseg * 32);
    const int brow = t >> 3;
    const int bseg = t & 7;
    const size_t   bOff = ((size_t)e * HID + brow) * DIM + n0 + bseg * 32;
    const uint32_t bDst = (uint32_t)(BOFF + brow * B_STR + bseg * 64);

    auto load_chunk = [&](int buf, int k0) {
        uint32_t bb = sbase + buf * SBUF;
        const __half* ap = g_h_h + aOff + k0;
        #pragma unroll
        for (int i = 0; i < 2; i++) cp16(bb + aDst + i * 16, ap + i * 8);
        const __half* bp = g_w2_h + bOff + (size_t)k0 * DIM;
        #pragma unroll
        for (int i = 0; i < 4; i++) cp16(bb + bDst + i * 16, bp + i * 8);
    };

    float d[2][8][4];
    #pragma unroll
    for (int i = 0; i < 2; i++)
        #pragma unroll
        for (int j = 0; j < 8; j++)
            #pragma unroll
            for (int q = 0; q < 4; q++) d[i][j][q] = 0.f;

    const uint32_t aFrag = (wm0 + (lane & 15)) * A_STR + (lane >> 4) * 16;
    const uint32_t bFrag = (lane & 15) * B_STR + wn0 * 2 + (lane >> 4) * 16;

    load_chunk(0, 0);
    cp_commit();
    cp_wait0();
    __syncthreads();

    const int NC = HID / TK;   // 64
    for (int ch = 0; ch < NC; ch++) {
        int buf = ch & 1;
        if (ch + 1 < NC) { load_chunk(buf ^ 1, (ch + 1) * TK); cp_commit(); }

        uint32_t Ab = sbase + buf * SBUF + aFrag;
        uint32_t Bb = sbase + buf * SBUF + BOFF + bFrag;
        #pragma unroll
        for (int ks = 0; ks < 4; ks++) {
            uint32_t a[2][4];
            #pragma unroll
            for (int mi = 0; mi < 2; mi++)
                LDSM_X4(a[mi], Ab + mi * 16 * A_STR + ks * 32);
            #pragma unroll
            for (int nj = 0; nj < 4; nj++) {
                uint32_t b[4];
                LDSM_X4T(b, Bb + ks * 16 * B_STR + nj * 32);
                #pragma unroll
                for (int mi = 0; mi < 2; mi++) {
                    MMA_F16(d[mi][2 * nj],     a[mi], b[0], b[1]);
                    MMA_F16(d[mi][2 * nj + 1], a[mi], b[2], b[3]);
                }
            }
        }
        if (ch + 1 < NC) { cp_wait0(); __syncthreads(); }
    }

    // epilogue: wt*(acc + b2) -> atomicAdd into out
    const int trow = lane >> 2;
    const int tcol = 2 * (lane & 3);
    #pragma unroll
    for (int mi = 0; mi < 2; mi++) {
        #pragma unroll
        for (int h2 = 0; h2 < 2; h2++) {
            int slot = m0 + wm0 + mi * 16 + trow + h2 * 8;
            if (slot < cnt) {
                int   tok = g_tok[e * TOK_MAX + slot];
                float wt  = g_wt [e * TOK_MAX + slot];
                float* orow = out + (size_t)tok * DIM;
                #pragma unroll
                for (int ni = 0; ni < 8; ni++) {
                    int col = n0 + wn0 + ni * 8 + tcol;
                    atomicAdd(orow + col,     wt * (d[mi][ni][h2 * 2 + 0] + __ldg(&b2[e * DIM + col])));
                    atomicAdd(orow + col + 1, wt * (d[mi][ni][h2 * 2 + 1] + __ldg(&b2[e * DIM + col + 1])));
                }
            }
        }
    }
}

// ---------------- launch ----------------
extern "C" void kernel_launch(void* const* d_in, const int* in_sizes, int n_in,
                              void* d_out, int out_size) {
    const float* x  = (const float*)d_in[0];
    const float* Wr = (const float*)d_in[1];
    const float* W1 = (const float*)d_in[2];
    const float* b1 = (const float*)d_in[3];
    const float* W2 = (const float*)d_in[4];
    const float* b2 = (const float*)d_in[5];
    float* out = (float*)d_out;

    const int T = in_sizes[0] / DIM;   // 8192 tokens

    cudaFuncSetAttribute(gemm1_mma, cudaFuncAttributeMaxDynamicSharedMemorySize, SMEM_DYN);
    cudaFuncSetAttribute(gemm2_mma, cudaFuncAttributeMaxDynamicSharedMemorySize, SMEM_DYN);

    cudaMemsetAsync(out, 0, (size_t)out_size * sizeof(float));

    reset_cnt_kernel<<<1, 32>>>();
    router_kernel<<<T, 128>>>(x, Wr);

    {
        int nx = T * DIM / 4;
        conv_f16_kernel<<<(nx + 255) / 256, 256>>>(x, 0, nx);
        int nw = NEXP * DIM * HID / 4;
        conv_f16_kernel<<<(nw + 255) / 256, 256>>>(W1, 1, nw);
        conv_f16_kernel<<<(nw + 255) / 256, 256>>>(W2, 2, nw);
    }

    dim3 gg1(TOK_MAX / TM, HID / TN, NEXP);   // (64, 16, 4)
    gemm1_mma<<<gg1, NTHR, SMEM_DYN>>>(b1);

    dim3 gg2(TOK_MAX / TM, DIM / TN, NEXP);   // (64, 4, 4)
    gemm2_mma<<<gg2, NTHR, SMEM_DYN>>>(b2, out);
}